// round 1
// baseline (speedup 1.0000x reference)
#include <cuda_runtime.h>
#include <cstdint>

// Problem constants (fixed by the reference):
#define T_DIM 1024
#define D_DIM 4096
#define O_DIM 4096
#define R_DIM 16

// GEMM tiling
#define BM 128
#define BN 128
#define BK 32
#define LDSS 36            // padded smem row stride (floats) -> conflict-free frag loads
#define KTILES (D_DIM / BK)
#define SMEM_BYTES (2 * 2 * BM * LDSS * 4)   // A + B, double buffered = 73728 B

// Scratch for LoRA activations (a[t,r]); device global => allowed (no allocs).
__device__ float g_act[T_DIM * R_DIM];

__device__ __forceinline__ uint32_t f2tf(float f) {
    uint32_t u;
    asm("cvt.rna.tf32.f32 %0, %1;" : "=r"(u) : "f"(f));
    return u;
}

__device__ __forceinline__ void mma_tf32(float* c, const uint32_t* a, const uint32_t* b) {
    asm volatile(
        "mma.sync.aligned.m16n8k8.row.col.f32.tf32.tf32.f32 "
        "{%0,%1,%2,%3}, {%4,%5,%6,%7}, {%8,%9}, {%0,%1,%2,%3};"
        : "+f"(c[0]), "+f"(c[1]), "+f"(c[2]), "+f"(c[3])
        : "r"(a[0]), "r"(a[1]), "r"(a[2]), "r"(a[3]), "r"(b[0]), "r"(b[1]));
}

// ---------------------------------------------------------------------------
// K1: LoRA shrink. a[t,r] = sum_d x[t,d] * A[idx_t, r, d]; 0 if idx<0.
// 1024 blocks (one per token), 512 threads = 16 warps, warp w handles r=w.
// ---------------------------------------------------------------------------
__global__ void lora_shrink_kernel(const float* __restrict__ x,
                                   const float* __restrict__ lora_a,
                                   const int* __restrict__ idxs) {
    int t = blockIdx.x;
    int w = threadIdx.x >> 5;    // r
    int lane = threadIdx.x & 31;
    int idx = idxs[t];
    if (idx < 0) {
        if (lane == 0) g_act[t * R_DIM + w] = 0.0f;
        return;
    }
    const float4* xa = reinterpret_cast<const float4*>(x + (size_t)t * D_DIM);
    const float4* aa = reinterpret_cast<const float4*>(
        lora_a + ((size_t)idx * R_DIM + w) * D_DIM);
    float acc = 0.0f;
#pragma unroll 4
    for (int i = lane; i < D_DIM / 4; i += 32) {
        float4 xv = xa[i];
        float4 av = aa[i];
        acc += xv.x * av.x + xv.y * av.y + xv.z * av.z + xv.w * av.w;
    }
#pragma unroll
    for (int off = 16; off; off >>= 1)
        acc += __shfl_xor_sync(0xffffffffu, acc, off);
    if (lane == 0) g_act[t * R_DIM + w] = acc;
}

// ---------------------------------------------------------------------------
// K2: base GEMM out = x @ W^T + bias, TF32 mma.sync, 128x128x32 tiles.
// 256 threads = 8 warps arranged 2 (m) x 4 (n); warp tile 64x32.
// ---------------------------------------------------------------------------
__global__ __launch_bounds__(256) void gemm_tf32_kernel(
    const float* __restrict__ X, const float* __restrict__ W,
    const float* __restrict__ bias, float* __restrict__ out) {
    extern __shared__ uint32_t smem[];
    uint32_t* As = smem;                         // [2][BM][LDSS]
    uint32_t* Bs = smem + 2 * BM * LDSS;         // [2][BN][LDSS]

    const int tid = threadIdx.x;
    const int bx = blockIdx.x, by = blockIdx.y;
    const int warp = tid >> 5, lane = tid & 31;
    const int wm = warp & 1;        // 0..1  -> 64 rows each
    const int wn = warp >> 1;       // 0..3  -> 32 cols each
    const int gid = lane >> 2;      // 0..7
    const int tig = lane & 3;       // 0..3

    // Global-load mapping: tile has 1024 float4 slots; 4 per thread.
    const int lr = tid >> 3;             // 0..31 (row within group of 32)
    const int lc = (tid & 7) * 4;        // col offset 0..28

    const float* Xblk = X + (size_t)(by * BM) * D_DIM;
    const float* Wblk = W + (size_t)(bx * BN) * D_DIM;

    float acc[4][4][4];
#pragma unroll
    for (int mi = 0; mi < 4; mi++)
#pragma unroll
        for (int ni = 0; ni < 4; ni++)
#pragma unroll
            for (int c = 0; c < 4; c++) acc[mi][ni][c] = 0.0f;

    float4 regA[4], regB[4];

    // prologue: tile 0
#pragma unroll
    for (int i = 0; i < 4; i++) {
        regA[i] = *reinterpret_cast<const float4*>(Xblk + (size_t)(lr + i * 32) * D_DIM + lc);
        regB[i] = *reinterpret_cast<const float4*>(Wblk + (size_t)(lr + i * 32) * D_DIM + lc);
    }
#pragma unroll
    for (int i = 0; i < 4; i++) {
        int ro = (lr + i * 32) * LDSS + lc;
        As[ro + 0] = f2tf(regA[i].x); As[ro + 1] = f2tf(regA[i].y);
        As[ro + 2] = f2tf(regA[i].z); As[ro + 3] = f2tf(regA[i].w);
        Bs[ro + 0] = f2tf(regB[i].x); Bs[ro + 1] = f2tf(regB[i].y);
        Bs[ro + 2] = f2tf(regB[i].z); Bs[ro + 3] = f2tf(regB[i].w);
    }
    __syncthreads();

    int buf = 0;
    for (int kt = 0; kt < KTILES; kt++) {
        if (kt < KTILES - 1) {
            int kb = (kt + 1) * BK;
#pragma unroll
            for (int i = 0; i < 4; i++) {
                regA[i] = *reinterpret_cast<const float4*>(
                    Xblk + (size_t)(lr + i * 32) * D_DIM + kb + lc);
                regB[i] = *reinterpret_cast<const float4*>(
                    Wblk + (size_t)(lr + i * 32) * D_DIM + kb + lc);
            }
        }

        const uint32_t* Ab = As + buf * BM * LDSS + wm * 64 * LDSS;
        const uint32_t* Bb = Bs + buf * BN * LDSS + wn * 32 * LDSS;
#pragma unroll
        for (int kk = 0; kk < 4; kk++) {
            const int kb = kk * 8;
            uint32_t af[4][4], bf[4][2];
#pragma unroll
            for (int mi = 0; mi < 4; mi++) {
                const uint32_t* p = Ab + (mi * 16 + gid) * LDSS + kb + tig;
                af[mi][0] = p[0];
                af[mi][1] = p[8 * LDSS];
                af[mi][2] = p[4];
                af[mi][3] = p[8 * LDSS + 4];
            }
#pragma unroll
            for (int ni = 0; ni < 4; ni++) {
                const uint32_t* p = Bb + (ni * 8 + gid) * LDSS + kb + tig;
                bf[ni][0] = p[0];
                bf[ni][1] = p[4];
            }
#pragma unroll
            for (int mi = 0; mi < 4; mi++)
#pragma unroll
                for (int ni = 0; ni < 4; ni++)
                    mma_tf32(acc[mi][ni], af[mi], bf[ni]);
        }

        if (kt < KTILES - 1) {
            int nbuf = buf ^ 1;
            uint32_t* Aw = As + nbuf * BM * LDSS;
            uint32_t* Bw = Bs + nbuf * BN * LDSS;
#pragma unroll
            for (int i = 0; i < 4; i++) {
                int ro = (lr + i * 32) * LDSS + lc;
                Aw[ro + 0] = f2tf(regA[i].x); Aw[ro + 1] = f2tf(regA[i].y);
                Aw[ro + 2] = f2tf(regA[i].z); Aw[ro + 3] = f2tf(regA[i].w);
                Bw[ro + 0] = f2tf(regB[i].x); Bw[ro + 1] = f2tf(regB[i].y);
                Bw[ro + 2] = f2tf(regB[i].z); Bw[ro + 3] = f2tf(regB[i].w);
            }
            __syncthreads();
            buf = nbuf;
        }
    }

    // Epilogue: out = acc + bias
#pragma unroll
    for (int mi = 0; mi < 4; mi++) {
        int row0 = by * BM + wm * 64 + mi * 16 + gid;
#pragma unroll
        for (int ni = 0; ni < 4; ni++) {
            int col0 = bx * BN + wn * 32 + ni * 8 + tig * 2;
            float b0 = bias[col0], b1 = bias[col0 + 1];
            float2 v0 = make_float2(acc[mi][ni][0] + b0, acc[mi][ni][1] + b1);
            float2 v1 = make_float2(acc[mi][ni][2] + b0, acc[mi][ni][3] + b1);
            *reinterpret_cast<float2*>(&out[(size_t)row0 * O_DIM + col0]) = v0;
            *reinterpret_cast<float2*>(&out[(size_t)(row0 + 8) * O_DIM + col0]) = v1;
        }
    }
}

// ---------------------------------------------------------------------------
// K3: LoRA expand. out[t,o] += sum_r a[t,r] * B[idx_t, o, r]. Block per token.
// ---------------------------------------------------------------------------
__global__ void lora_expand_kernel(const float* __restrict__ lora_b,
                                   const int* __restrict__ idxs,
                                   float* __restrict__ out) {
    int t = blockIdx.x;
    int idx = idxs[t];
    if (idx < 0) return;
    __shared__ float sa[R_DIM];
    if (threadIdx.x < R_DIM) sa[threadIdx.x] = g_act[t * R_DIM + threadIdx.x];
    __syncthreads();
    float ar[R_DIM];
#pragma unroll
    for (int r = 0; r < R_DIM; r++) ar[r] = sa[r];

    const float4* B4 = reinterpret_cast<const float4*>(
        lora_b + (size_t)idx * O_DIM * R_DIM);
    float* orow = out + (size_t)t * O_DIM;
    for (int o = threadIdx.x; o < O_DIM; o += blockDim.x) {
        const float4* bp = B4 + o * 4;
        float4 v0 = bp[0], v1 = bp[1], v2 = bp[2], v3 = bp[3];
        float y = ar[0] * v0.x + ar[1] * v0.y + ar[2] * v0.z + ar[3] * v0.w
                + ar[4] * v1.x + ar[5] * v1.y + ar[6] * v1.z + ar[7] * v1.w
                + ar[8] * v2.x + ar[9] * v2.y + ar[10] * v2.z + ar[11] * v2.w
                + ar[12] * v3.x + ar[13] * v3.y + ar[14] * v3.z + ar[15] * v3.w;
        orow[o] += y;
    }
}

// ---------------------------------------------------------------------------
extern "C" void kernel_launch(void* const* d_in, const int* in_sizes, int n_in,
                              void* d_out, int out_size) {
    const float* x    = (const float*)d_in[0];   // [T, D]
    const float* w    = (const float*)d_in[1];   // [O, D]
    const float* bias = (const float*)d_in[2];   // [O]
    const float* la   = (const float*)d_in[3];   // [L,1,R,D]
    const float* lb   = (const float*)d_in[4];   // [L,1,O,R]
    const int* idxs   = (const int*)d_in[5];     // [T]
    float* out        = (float*)d_out;           // [T, O]

    cudaFuncSetAttribute(gemm_tf32_kernel,
                         cudaFuncAttributeMaxDynamicSharedMemorySize, SMEM_BYTES);

    lora_shrink_kernel<<<T_DIM, 512>>>(x, la, idxs);

    dim3 grid(O_DIM / BN, T_DIM / BM);
    gemm_tf32_kernel<<<grid, 256, SMEM_BYTES>>>(x, w, bias, out);

    lora_expand_kernel<<<T_DIM, 256>>>(lb, idxs, out);
}